// round 1
// baseline (speedup 1.0000x reference)
#include <cuda_runtime.h>

// ---------------------------------------------------------------------------
// Problem shapes (fixed for PQHotShared_33938831573580)
// ---------------------------------------------------------------------------
#define N_ROWS_U 16384
#define RANK     64
#define N_COLS_B 4096
#define KCB      2048
#define DS       16
#define SUBS_U   (N_ROWS_U * RANK / DS)   // 65536
#define SUBS_B   (RANK * N_COLS_B / DS)   // 16384
#define TOTAL_SUBS (SUBS_U + SUBS_B)      // 81920
#define TILE_CW   512                     // codewords per smem tile
#define TILE_PAIR 256                     // pairs per smem tile

// Scratch (static device allocations are the allowed scratch mechanism)
__device__ float g_UqT[RANK * N_ROWS_U];  // quantized U, TRANSPOSED: [k][row]
__device__ float g_Bq [RANK * N_COLS_B];  // quantized B: [k][n] (natural layout)

typedef unsigned long long u64t;

// ---------------------------------------------------------------------------
// Packed f32x2 helpers (Blackwell FFMA2 path — only reachable via PTX)
// ---------------------------------------------------------------------------
__device__ __forceinline__ u64t pack2(float a, float b) {
    u64t r;
    asm("mov.b64 %0, {%1, %2};" : "=l"(r)
        : "r"(__float_as_uint(a)), "r"(__float_as_uint(b)));
    return r;
}
__device__ __forceinline__ void unpack2(u64t v, float& a, float& b) {
    unsigned lo, hi;
    asm("mov.b64 {%0, %1}, %2;" : "=r"(lo), "=r"(hi) : "l"(v));
    a = __uint_as_float(lo);
    b = __uint_as_float(hi);
}
__device__ __forceinline__ u64t ffma2(u64t a, u64t b, u64t c) {
    u64t d;
    asm("fma.rn.f32x2 %0, %1, %2, %3;" : "=l"(d) : "l"(a), "l"(b), "l"(c));
    return d;
}
__device__ __forceinline__ u64t fadd2(u64t a, u64t b) {
    u64t d;
    asm("add.rn.f32x2 %0, %1, %2;" : "=l"(d) : "l"(a), "l"(b));
    return d;
}

// ---------------------------------------------------------------------------
// Kernel 1: PQ quantization of both U and B against the shared codebook.
//
// score_k = g . c_k - 0.5*||c_k||^2  (argmax == reference argmin of d2,
// first-wins tie order preserved by strict '>' and ascending k).
// Codebook is processed in 4 smem tiles of 512 codewords, laid out in an
// interleaved pair format so each f32x2 lane scores one codeword.
// U's dequantized output is written TRANSPOSED so the GEMM's A-tile smem
// stores are conflict-free STS.128.
// ---------------------------------------------------------------------------
__global__ __launch_bounds__(256) void quant_kernel(
    const float* __restrict__ U, const float* __restrict__ Bm,
    const float* __restrict__ rsU, const float* __restrict__ rsB,
    const float* __restrict__ cb)
{
    // s_cb[p*32 + 2*i + h] = cb[tile*512 + 2*p + h][i]   (pair-interleaved)
    __shared__ float s_cb[TILE_PAIR * 2 * DS];   // 32 KB
    __shared__ float s_bias[TILE_CW];            // -0.5*||c||^2, 2 KB

    const int tid = threadIdx.x;
    const int chunk = (TOTAL_SUBS + gridDim.x - 1) / gridDim.x;
    const int start = blockIdx.x * chunk;
    const int end   = min(start + chunk, TOTAL_SUBS);

    for (int sbase = start; sbase < end; sbase += 256) {
        const int s = sbase + tid;
        const bool active = (s < end);

        // ---- load this thread's subvector, scaled and lane-duplicated ----
        u64t gd[DS];
        float rsv = 1.0f;
        const float* W = U;
        int s2 = 0;
        if (active) {
            if (s < SUBS_U) {
                W   = U + (size_t)s * DS;
                rsv = rsU[s >> 2];                 // 4 subvecs per U row
            } else {
                s2  = s - SUBS_U;
                W   = Bm + (size_t)s2 * DS;
                rsv = rsB[s2 >> 8];                // 256 subvecs per B row
            }
            const float inv = 1.0f / rsv;
            const float4* w4 = (const float4*)W;
            #pragma unroll
            for (int q = 0; q < 4; ++q) {
                float4 v = w4[q];
                float g0 = v.x * inv, g1 = v.y * inv, g2 = v.z * inv, g3 = v.w * inv;
                gd[4*q+0] = pack2(g0, g0);
                gd[4*q+1] = pack2(g1, g1);
                gd[4*q+2] = pack2(g2, g2);
                gd[4*q+3] = pack2(g3, g3);
            }
        }

        float best = -3.402823466e38f;
        int   bidx = 0;

        for (int t = 0; t < KCB / TILE_CW; ++t) {
            __syncthreads();   // previous tile fully consumed

            // ---- bias (codeword norms), conflict-free ----
            for (int c = tid; c < TILE_CW; c += 256) {
                const float4* p4 = (const float4*)(cb + (size_t)(t * TILE_CW + c) * DS);
                float4 a = p4[0], b = p4[1], cc = p4[2], d = p4[3];
                float n = a.x*a.x + a.y*a.y + a.z*a.z + a.w*a.w
                        + b.x*b.x + b.y*b.y + b.z*b.z + b.w*b.w
                        + cc.x*cc.x + cc.y*cc.y + cc.z*cc.z + cc.w*cc.w
                        + d.x*d.x + d.y*d.y + d.z*d.z + d.w*d.w;
                s_bias[c] = -0.5f * n;
            }
            // ---- pair-interleaved codebook tile, conflict-free STS.32 ----
            {
                const int h   = tid & 1;
                const int ii  = (tid >> 1) & 15;
                const int grp = tid >> 5;
                for (int p = grp; p < TILE_PAIR; p += 8) {
                    s_cb[p * 32 + 2 * ii + h] =
                        cb[(size_t)(t * TILE_CW + 2 * p + h) * DS + ii];
                }
            }
            __syncthreads();

            if (active) {
                for (int p = 0; p < TILE_PAIR; p += 2) {
                    const ulonglong2* q0 = (const ulonglong2*)(s_cb + p * 32);
                    const ulonglong2* q1 = (const ulonglong2*)(s_cb + (p + 1) * 32);
                    u64t a0 = *(const u64t*)(s_bias + 2 * p);
                    u64t a1 = *(const u64t*)(s_bias + 2 * p + 2);
                    u64t b0 = 0ull, b1 = 0ull;
                    #pragma unroll
                    for (int j = 0; j < 8; ++j) {
                        ulonglong2 v0 = q0[j];
                        ulonglong2 v1 = q1[j];
                        a0 = ffma2(gd[2*j],   v0.x, a0);
                        b0 = ffma2(gd[2*j+1], v0.y, b0);
                        a1 = ffma2(gd[2*j],   v1.x, a1);
                        b1 = ffma2(gd[2*j+1], v1.y, b1);
                    }
                    float sc0, sc1, sc2, sc3;
                    unpack2(fadd2(a0, b0), sc0, sc1);
                    unpack2(fadd2(a1, b1), sc2, sc3);
                    const int kb = t * TILE_CW + 2 * p;
                    if (sc0 > best) { best = sc0; bidx = kb;     }
                    if (sc1 > best) { best = sc1; bidx = kb + 1; }
                    if (sc2 > best) { best = sc2; bidx = kb + 2; }
                    if (sc3 > best) { best = sc3; bidx = kb + 3; }
                }
            }
        }

        // ---- dequantize + rescale + write ----
        if (active) {
            const float4* c4 = (const float4*)(cb + (size_t)bidx * DS);
            float cw[DS];
            #pragma unroll
            for (int q = 0; q < 4; ++q) {
                float4 v = c4[q];
                cw[4*q+0] = v.x * rsv; cw[4*q+1] = v.y * rsv;
                cw[4*q+2] = v.z * rsv; cw[4*q+3] = v.w * rsv;
            }
            if (s < SUBS_U) {
                // transposed write: g_UqT[k][row]
                const int row   = s >> 2;
                const int kbase = (s & 3) * DS;
                #pragma unroll
                for (int i = 0; i < DS; ++i)
                    g_UqT[(size_t)(kbase + i) * N_ROWS_U + row] = cw[i];
            } else {
                float4* o = (float4*)(g_Bq + (size_t)s2 * DS);
                o[0] = make_float4(cw[0],  cw[1],  cw[2],  cw[3]);
                o[1] = make_float4(cw[4],  cw[5],  cw[6],  cw[7]);
                o[2] = make_float4(cw[8],  cw[9],  cw[10], cw[11]);
                o[3] = make_float4(cw[12], cw[13], cw[14], cw[15]);
            }
        }
    }
}

// ---------------------------------------------------------------------------
// Kernel 2: out[16384,4096] = Uq @ Bq, K = 64, fp32 with FFMA2.
// CTA tile 128(M) x 64(N), 256 threads, per-thread 8m x 4n (2 f32x2 pairs).
// Both operands already live k-major in scratch -> conflict-free STS.128.
// ---------------------------------------------------------------------------
#define BM 128
#define BN 64

__global__ __launch_bounds__(256, 2) void gemm_kernel(float* __restrict__ out)
{
    __shared__ float As[RANK][BM];   // 32 KB
    __shared__ float Bs[RANK][BN];   // 16 KB

    const int tid = threadIdx.x;
    const int m0 = blockIdx.y * BM;
    const int n0 = blockIdx.x * BN;

    // A tile: g_UqT[k][m0 + m], coalesced LDG.128 / conflict-free STS.128
    for (int i = tid; i < RANK * (BM / 4); i += 256) {
        const int k  = i >> 5;
        const int m4 = (i & 31) << 2;
        *(float4*)&As[k][m4] = *(const float4*)&g_UqT[(size_t)k * N_ROWS_U + m0 + m4];
    }
    // B tile: g_Bq[k][n0 + n]
    for (int i = tid; i < RANK * (BN / 4); i += 256) {
        const int k  = i >> 4;
        const int n4 = (i & 15) << 2;
        *(float4*)&Bs[k][n4] = *(const float4*)&g_Bq[(size_t)k * N_COLS_B + n0 + n4];
    }
    __syncthreads();

    const int tx = tid & 15;        // n direction
    const int ty = tid >> 4;        // m direction
    const float* ap = &As[0][ty * 8];
    const float* bp = &Bs[0][tx * 4];

    u64t acc[8][2];
    #pragma unroll
    for (int m = 0; m < 8; ++m) { acc[m][0] = 0ull; acc[m][1] = 0ull; }

    #pragma unroll 8
    for (int k = 0; k < RANK; ++k) {
        float4 a0 = *(const float4*)(ap + k * BM);
        float4 a1 = *(const float4*)(ap + k * BM + 4);
        ulonglong2 bb = *(const ulonglong2*)(bp + k * BN);
        u64t ad[8];
        ad[0] = pack2(a0.x, a0.x); ad[1] = pack2(a0.y, a0.y);
        ad[2] = pack2(a0.z, a0.z); ad[3] = pack2(a0.w, a0.w);
        ad[4] = pack2(a1.x, a1.x); ad[5] = pack2(a1.y, a1.y);
        ad[6] = pack2(a1.z, a1.z); ad[7] = pack2(a1.w, a1.w);
        #pragma unroll
        for (int m = 0; m < 8; ++m) {
            acc[m][0] = ffma2(ad[m], bb.x, acc[m][0]);
            acc[m][1] = ffma2(ad[m], bb.y, acc[m][1]);
        }
    }

    #pragma unroll
    for (int m = 0; m < 8; ++m) {
        float x0, x1, x2, x3;
        unpack2(acc[m][0], x0, x1);
        unpack2(acc[m][1], x2, x3);
        *(float4*)&out[(size_t)(m0 + ty * 8 + m) * N_COLS_B + n0 + tx * 4] =
            make_float4(x0, x1, x2, x3);
    }
}

// ---------------------------------------------------------------------------
// Launch
// ---------------------------------------------------------------------------
extern "C" void kernel_launch(void* const* d_in, const int* in_sizes, int n_in,
                              void* d_out, int out_size)
{
    const float *U = nullptr, *B = nullptr, *rsU = nullptr, *rsB = nullptr, *cb = nullptr;
    for (int i = 0; i < n_in; ++i) {
        switch (in_sizes[i]) {
            case N_ROWS_U * RANK:  U   = (const float*)d_in[i]; break;  // 1048576
            case RANK * N_COLS_B:  B   = (const float*)d_in[i]; break;  // 262144
            case N_ROWS_U:         rsU = (const float*)d_in[i]; break;  // 16384
            case RANK:             rsB = (const float*)d_in[i]; break;  // 64
            case KCB * DS:         cb  = (const float*)d_in[i]; break;  // 32768
            default: break;
        }
    }
    // positional fallback (metadata order: U, B, rs_U, rs_B, codebook)
    if (!U || !B || !rsU || !rsB || !cb) {
        U   = (const float*)d_in[0];
        B   = (const float*)d_in[1];
        rsU = (const float*)d_in[2];
        rsB = (const float*)d_in[3];
        cb  = (const float*)d_in[4];
    }

    quant_kernel<<<296, 256>>>(U, B, rsU, rsB, cb);
    gemm_kernel<<<dim3(N_COLS_B / BN, N_ROWS_U / BM), 256>>>((float*)d_out);
}

// round 3
// speedup vs baseline: 1.0128x; 1.0128x over previous
#include <cuda_runtime.h>

// ---------------------------------------------------------------------------
// Problem shapes (fixed for PQHotShared_33938831573580)
// ---------------------------------------------------------------------------
#define N_ROWS_U 16384
#define RANK     64
#define N_COLS_B 4096
#define KCB      2048
#define DS       16
#define SUBS_U   (N_ROWS_U * RANK / DS)   // 65536
#define SUBS_B   (RANK * N_COLS_B / DS)   // 16384
#define TOTAL_SUBS (SUBS_U + SUBS_B)      // 81920
#define TILE_CW   512                     // codewords per smem tile
#define TILE_PAIR 256                     // pairs per smem tile

// Scratch
__device__ float g_UqT[RANK * N_ROWS_U];  // quantized U, TRANSPOSED: [k][row]
__device__ float g_Bq [RANK * N_COLS_B];  // quantized B: [k][n]

typedef unsigned long long u64t;

// ---------------------------------------------------------------------------
// Packed f32x2 helpers
// ---------------------------------------------------------------------------
__device__ __forceinline__ u64t pack2(float a, float b) {
    u64t r;
    asm("mov.b64 %0, {%1, %2};" : "=l"(r)
        : "r"(__float_as_uint(a)), "r"(__float_as_uint(b)));
    return r;
}
__device__ __forceinline__ void unpack2(u64t v, float& a, float& b) {
    unsigned lo, hi;
    asm("mov.b64 {%0, %1}, %2;" : "=r"(lo), "=r"(hi) : "l"(v));
    a = __uint_as_float(lo);
    b = __uint_as_float(hi);
}
__device__ __forceinline__ u64t ffma2(u64t a, u64t b, u64t c) {
    u64t d;
    asm("fma.rn.f32x2 %0, %1, %2, %3;" : "=l"(d) : "l"(a), "l"(b), "l"(c));
    return d;
}
__device__ __forceinline__ u64t fadd2(u64t a, u64t b) {
    u64t d;
    asm("add.rn.f32x2 %0, %1, %2;" : "=l"(d) : "l"(a), "l"(b));
    return d;
}

// ---------------------------------------------------------------------------
// Kernel 1: PQ quantization. 640 CTAs x 128 threads = exactly 81920
// subvectors, one per thread — no idle-lane tail at all.
// score_k = g.c_k - 0.5*||c_k||^2 (argmax == ref argmin, first-wins ties).
// ---------------------------------------------------------------------------
__global__ __launch_bounds__(128) void quant_kernel(
    const float* __restrict__ U, const float* __restrict__ Bm,
    const float* __restrict__ rsU, const float* __restrict__ rsB,
    const float* __restrict__ cb)
{
    // s_cb[p*32 + 2*i + h] = cb[tile*512 + 2*p + h][i]   (pair-interleaved)
    __shared__ float s_cb[TILE_PAIR * 2 * DS];   // 32 KB
    __shared__ float s_bias[TILE_CW];            // 2 KB

    const int tid = threadIdx.x;
    const int s   = blockIdx.x * 128 + tid;      // 0 .. 81919, always valid

    // ---- load this thread's subvector, scaled and lane-duplicated ----
    u64t gd[DS];
    float rsv;
    const float* W;
    int s2 = 0;
    if (s < SUBS_U) {
        W   = U + (size_t)s * DS;
        rsv = rsU[s >> 2];                 // 4 subvecs per U row
    } else {
        s2  = s - SUBS_U;
        W   = Bm + (size_t)s2 * DS;
        rsv = rsB[s2 >> 8];                // 256 subvecs per B row
    }
    {
        const float inv = 1.0f / rsv;
        const float4* w4 = (const float4*)W;
        #pragma unroll
        for (int q = 0; q < 4; ++q) {
            float4 v = w4[q];
            float g0 = v.x * inv, g1 = v.y * inv, g2 = v.z * inv, g3 = v.w * inv;
            gd[4*q+0] = pack2(g0, g0);
            gd[4*q+1] = pack2(g1, g1);
            gd[4*q+2] = pack2(g2, g2);
            gd[4*q+3] = pack2(g3, g3);
        }
    }

    float best = -3.402823466e38f;
    int   bidx = 0;

    for (int t = 0; t < KCB / TILE_CW; ++t) {
        __syncthreads();   // previous tile fully consumed

        // ---- bias (codeword norms) ----
        for (int c = tid; c < TILE_CW; c += 128) {
            const float4* p4 = (const float4*)(cb + (size_t)(t * TILE_CW + c) * DS);
            float4 a = p4[0], b = p4[1], cc = p4[2], d = p4[3];
            float n = a.x*a.x + a.y*a.y + a.z*a.z + a.w*a.w
                    + b.x*b.x + b.y*b.y + b.z*b.z + b.w*b.w
                    + cc.x*cc.x + cc.y*cc.y + cc.z*cc.z + cc.w*cc.w
                    + d.x*d.x + d.y*d.y + d.z*d.z + d.w*d.w;
            s_bias[c] = -0.5f * n;
        }
        // ---- pair-interleaved codebook tile ----
        {
            const int h   = tid & 1;
            const int ii  = (tid >> 1) & 15;
            const int grp = tid >> 5;          // 0..3
            for (int p = grp; p < TILE_PAIR; p += 4) {
                s_cb[p * 32 + 2 * ii + h] =
                    cb[(size_t)(t * TILE_CW + 2 * p + h) * DS + ii];
            }
        }
        __syncthreads();

        for (int p = 0; p < TILE_PAIR; p += 2) {
            const ulonglong2* q0 = (const ulonglong2*)(s_cb + p * 32);
            const ulonglong2* q1 = (const ulonglong2*)(s_cb + (p + 1) * 32);
            u64t a0 = *(const u64t*)(s_bias + 2 * p);
            u64t a1 = *(const u64t*)(s_bias + 2 * p + 2);
            u64t b0 = 0ull, b1 = 0ull;
            #pragma unroll
            for (int j = 0; j < 8; ++j) {
                ulonglong2 v0 = q0[j];
                ulonglong2 v1 = q1[j];
                a0 = ffma2(gd[2*j],   v0.x, a0);
                b0 = ffma2(gd[2*j+1], v0.y, b0);
                a1 = ffma2(gd[2*j],   v1.x, a1);
                b1 = ffma2(gd[2*j+1], v1.y, b1);
            }
            float sc0, sc1, sc2, sc3;
            unpack2(fadd2(a0, b0), sc0, sc1);
            unpack2(fadd2(a1, b1), sc2, sc3);
            const int kb = t * TILE_CW + 2 * p;
            if (sc0 > best) { best = sc0; bidx = kb;     }
            if (sc1 > best) { best = sc1; bidx = kb + 1; }
            if (sc2 > best) { best = sc2; bidx = kb + 2; }
            if (sc3 > best) { best = sc3; bidx = kb + 3; }
        }
    }

    // ---- dequantize + rescale + write ----
    {
        const float4* c4 = (const float4*)(cb + (size_t)bidx * DS);
        float cw[DS];
        #pragma unroll
        for (int q = 0; q < 4; ++q) {
            float4 v = c4[q];
            cw[4*q+0] = v.x * rsv; cw[4*q+1] = v.y * rsv;
            cw[4*q+2] = v.z * rsv; cw[4*q+3] = v.w * rsv;
        }
        if (s < SUBS_U) {
            const int row   = s >> 2;
            const int kbase = (s & 3) * DS;
            #pragma unroll
            for (int i = 0; i < DS; ++i)
                g_UqT[(size_t)(kbase + i) * N_ROWS_U + row] = cw[i];
        } else {
            float4* o = (float4*)(g_Bq + (size_t)s2 * DS);
            o[0] = make_float4(cw[0],  cw[1],  cw[2],  cw[3]);
            o[1] = make_float4(cw[4],  cw[5],  cw[6],  cw[7]);
            o[2] = make_float4(cw[8],  cw[9],  cw[10], cw[11]);
            o[3] = make_float4(cw[12], cw[13], cw[14], cw[15]);
        }
    }
}

// ---------------------------------------------------------------------------
// Kernel 2: out = Uq @ Bq, K=64 fp32 FFMA2.
// CTA tile 128x128, 256 threads, per-thread 16m x 4n as 8 m-pairs x 4 n.
//   - A pairs: adjacent m values -> direct LDS, NO packing movs.
//   - B scalars duplicated in smem -> (b,b) pairs straight from LDS.128.
// Per k per thread: 6 LDS.128 + 32 FFMA2 + 0 movs.
// Dynamic smem 96 KB (As 32K + Bdup 64K), 2 CTAs/SM.
// ---------------------------------------------------------------------------
#define BM 128
#define BN 128

__global__ __launch_bounds__(256, 2) void gemm_kernel(float* __restrict__ out)
{
    extern __shared__ float smem[];
    float* As  = smem;                 // [64][128]
    float* Bs2 = smem + RANK * BM;     // [64][256] duplicated

    const int tid = threadIdx.x;
    const int m0 = blockIdx.y * BM;
    const int n0 = blockIdx.x * BN;

    // A tile: g_UqT[k][m0+m] (k-major), coalesced, conflict-free
    #pragma unroll
    for (int it = 0; it < 8; ++it) {
        const int idx = tid + it * 256;          // 0..2047
        const int k  = idx >> 5;
        const int m4 = (idx & 31) << 2;
        *(float4*)&As[k * BM + m4] =
            *(const float4*)&g_UqT[(size_t)k * N_ROWS_U + m0 + m4];
    }
    // B tile duplicated: Bs2[k][2n]=Bs2[k][2n+1]=Bq[k][n0+n]
    #pragma unroll
    for (int it = 0; it < 8; ++it) {
        const int idx = tid + it * 256;          // 0..2047
        const int k  = idx >> 5;
        const int n4 = (idx & 31) << 2;
        float4 v = *(const float4*)&g_Bq[(size_t)k * N_COLS_B + n0 + n4];
        float* dst = &Bs2[k * (2 * BN) + 2 * n4];
        *(float4*)(dst)     = make_float4(v.x, v.x, v.y, v.y);
        *(float4*)(dst + 4) = make_float4(v.z, v.z, v.w, v.w);
    }
    __syncthreads();

    const int tx = tid & 31;        // n direction (0..31), 4 cols each
    const int ty = tid >> 5;        // m direction (0..7), 16 rows each

    const float* ap = As + ty * 16;         // warp-broadcast reads
    const float* bp = Bs2 + tx * 8;         // bank-spanning reads

    u64t acc[8][4];
    #pragma unroll
    for (int i = 0; i < 8; ++i)
        #pragma unroll
        for (int j = 0; j < 4; ++j) acc[i][j] = 0ull;

    #pragma unroll 4
    for (int k = 0; k < RANK; ++k) {
        // 16 A floats = 8 adjacent-m pairs, zero packing
        ulonglong2 A0 = *(const ulonglong2*)(ap + k * BM);
        ulonglong2 A1 = *(const ulonglong2*)(ap + k * BM + 4);
        ulonglong2 A2 = *(const ulonglong2*)(ap + k * BM + 8);
        ulonglong2 A3 = *(const ulonglong2*)(ap + k * BM + 12);
        // 4 duplicated B pairs
        ulonglong2 B0 = *(const ulonglong2*)(bp + k * (2 * BN));
        ulonglong2 B1 = *(const ulonglong2*)(bp + k * (2 * BN) + 4);
        u64t ad[8] = {A0.x, A0.y, A1.x, A1.y, A2.x, A2.y, A3.x, A3.y};
        u64t bd[4] = {B0.x, B0.y, B1.x, B1.y};
        #pragma unroll
        for (int i = 0; i < 8; ++i) {
            #pragma unroll
            for (int j = 0; j < 4; ++j)
                acc[i][j] = ffma2(ad[i], bd[j], acc[i][j]);
        }
    }

    // Epilogue: per m-pair i, rows r=(m0+16ty+2i), r+1; cols n0+4tx..+3.
    #pragma unroll
    for (int i = 0; i < 8; ++i) {
        float l0, h0, l1, h1, l2, h2, l3, h3;
        unpack2(acc[i][0], l0, h0);
        unpack2(acc[i][1], l1, h1);
        unpack2(acc[i][2], l2, h2);
        unpack2(acc[i][3], l3, h3);
        const size_t r = (size_t)(m0 + ty * 16 + 2 * i);
        float* o0 = out + r * N_COLS_B + n0 + tx * 4;
        *(float4*)o0              = make_float4(l0, l1, l2, l3);
        *(float4*)(o0 + N_COLS_B) = make_float4(h0, h1, h2, h3);
    }
}

// ---------------------------------------------------------------------------
// Launch
// ---------------------------------------------------------------------------
extern "C" void kernel_launch(void* const* d_in, const int* in_sizes, int n_in,
                              void* d_out, int out_size)
{
    const float *U = nullptr, *B = nullptr, *rsU = nullptr, *rsB = nullptr, *cb = nullptr;
    for (int i = 0; i < n_in; ++i) {
        switch (in_sizes[i]) {
            case N_ROWS_U * RANK:  U   = (const float*)d_in[i]; break;
            case RANK * N_COLS_B:  B   = (const float*)d_in[i]; break;
            case N_ROWS_U:         rsU = (const float*)d_in[i]; break;
            case RANK:             rsB = (const float*)d_in[i]; break;
            case KCB * DS:         cb  = (const float*)d_in[i]; break;
            default: break;
        }
    }
    if (!U || !B || !rsU || !rsB || !cb) {
        U   = (const float*)d_in[0];
        B   = (const float*)d_in[1];
        rsU = (const float*)d_in[2];
        rsB = (const float*)d_in[3];
        cb  = (const float*)d_in[4];
    }

    const int smem_bytes = (RANK * BM + RANK * 2 * BN) * (int)sizeof(float); // 96 KB
    cudaFuncSetAttribute(gemm_kernel,
                         cudaFuncAttributeMaxDynamicSharedMemorySize, smem_bytes);

    quant_kernel<<<TOTAL_SUBS / 128, 128>>>(U, B, rsU, rsB, cb);
    gemm_kernel<<<dim3(N_COLS_B / BN, N_ROWS_U / BM), 256, smem_bytes>>>((float*)d_out);
}

// round 7
// speedup vs baseline: 1.0941x; 1.0803x over previous
#include <cuda_runtime.h>
#include <cuda_bf16.h>
#include <cstdint>

// ---------------------------------------------------------------------------
// Problem shapes (fixed)
// ---------------------------------------------------------------------------
#define N_ROWS_U 16384
#define RANK     64
#define N_COLS_B 4096
#define KCB      2048
#define DS       16
#define SUBS_U   (N_ROWS_U * RANK / DS)   // 65536
#define SUBS_B   (RANK * N_COLS_B / DS)   // 16384
#define TOTAL_SUBS (SUBS_U + SUBS_B)      // 81920
#define TILE_CW   512
#define TILE_PAIR 256

// Split-bf16 K-concat: K_ext = 192 = [hi | lo | hi]_A  x  [hi | hi | lo]_B
#define KE 192

// Plain row-major staged operands (k contiguous = mma.sync row.col layout)
__device__ __align__(16) unsigned short g_Aext[(size_t)N_ROWS_U * KE]; // 6.3 MB
__device__ __align__(16) unsigned short g_Bext[(size_t)N_COLS_B * KE]; // 1.6 MB

typedef unsigned long long u64t;

// ---------------------------------------------------------------------------
// Packed f32x2 helpers (quant kernel scoring)
// ---------------------------------------------------------------------------
__device__ __forceinline__ u64t pack2(float a, float b) {
    u64t r;
    asm("mov.b64 %0, {%1, %2};" : "=l"(r)
        : "r"(__float_as_uint(a)), "r"(__float_as_uint(b)));
    return r;
}
__device__ __forceinline__ void unpack2(u64t v, float& a, float& b) {
    unsigned lo, hi;
    asm("mov.b64 {%0, %1}, %2;" : "=r"(lo), "=r"(hi) : "l"(v));
    a = __uint_as_float(lo);
    b = __uint_as_float(hi);
}
__device__ __forceinline__ u64t ffma2(u64t a, u64t b, u64t c) {
    u64t d;
    asm("fma.rn.f32x2 %0, %1, %2, %3;" : "=l"(d) : "l"(a), "l"(b), "l"(c));
    return d;
}
__device__ __forceinline__ u64t fadd2(u64t a, u64t b) {
    u64t d;
    asm("add.rn.f32x2 %0, %1, %2;" : "=l"(d) : "l"(a), "l"(b));
    return d;
}

// Strict fma chains, bitwise-reproducible (needed for exact argmax recompute)
__device__ __forceinline__ float bias_of(const float* row) {
    float n = row[0] * row[0];
    #pragma unroll
    for (int i = 1; i < DS; ++i) n = fmaf(row[i], row[i], n);
    return -0.5f * n;
}
__device__ __forceinline__ float score_of(const float* g, const float* row, float bias) {
    float A = bias, B = 0.0f;
    #pragma unroll
    for (int j = 0; j < 8; ++j) {
        A = fmaf(g[2 * j],     row[2 * j],     A);
        B = fmaf(g[2 * j + 1], row[2 * j + 1], B);
    }
    return A + B;
}

// ---------------------------------------------------------------------------
// Kernel 1: PQ quantization. 640 CTAs x 128 threads = 81920 subvectors.
// score_k = g.c_k - 0.5*||c_k||^2; argmax == ref argmin, first-wins ties.
// FMNMX group-max in the hot loop; exact bitwise recompute of the winning
// group of 4 at the end (same fma chains -> identical selection).
// Writes split-bf16 extended operands for the HMMA GEMM.
// ---------------------------------------------------------------------------
__global__ __launch_bounds__(128) void quant_kernel(
    const float* __restrict__ U, const float* __restrict__ Bm,
    const float* __restrict__ rsU, const float* __restrict__ rsB,
    const float* __restrict__ cb)
{
    __shared__ float s_cb[TILE_PAIR * 2 * DS];   // 32 KB pair-interleaved
    __shared__ float s_bias[TILE_CW];            // 2 KB

    const int tid = threadIdx.x;
    const int s   = blockIdx.x * 128 + tid;

    u64t gd[DS];
    float rsv;
    const float* W;
    int s2 = 0;
    if (s < SUBS_U) {
        W   = U + (size_t)s * DS;
        rsv = rsU[s >> 2];
    } else {
        s2  = s - SUBS_U;
        W   = Bm + (size_t)s2 * DS;
        rsv = rsB[s2 >> 8];
    }
    const float inv = 1.0f / rsv;
    {
        const float4* w4 = (const float4*)W;
        #pragma unroll
        for (int q = 0; q < 4; ++q) {
            float4 v = w4[q];
            float g0 = v.x * inv, g1 = v.y * inv, g2 = v.z * inv, g3 = v.w * inv;
            gd[4*q+0] = pack2(g0, g0);
            gd[4*q+1] = pack2(g1, g1);
            gd[4*q+2] = pack2(g2, g2);
            gd[4*q+3] = pack2(g3, g3);
        }
    }

    float best  = -3.402823466e38f;
    int   gbase = 0;

    for (int t = 0; t < KCB / TILE_CW; ++t) {
        __syncthreads();
        for (int c = tid; c < TILE_CW; c += 128)
            s_bias[c] = bias_of(cb + (size_t)(t * TILE_CW + c) * DS);
        {
            const int h   = tid & 1;
            const int ii  = (tid >> 1) & 15;
            const int grp = tid >> 5;
            for (int p = grp; p < TILE_PAIR; p += 4)
                s_cb[p * 32 + 2 * ii + h] =
                    cb[(size_t)(t * TILE_CW + 2 * p + h) * DS + ii];
        }
        __syncthreads();

        for (int p = 0; p < TILE_PAIR; p += 2) {
            const ulonglong2* q0 = (const ulonglong2*)(s_cb + p * 32);
            const ulonglong2* q1 = (const ulonglong2*)(s_cb + (p + 1) * 32);
            u64t a0 = *(const u64t*)(s_bias + 2 * p);
            u64t a1 = *(const u64t*)(s_bias + 2 * p + 2);
            u64t b0 = 0ull, b1 = 0ull;
            #pragma unroll
            for (int j = 0; j < 8; ++j) {
                ulonglong2 v0 = q0[j];
                ulonglong2 v1 = q1[j];
                a0 = ffma2(gd[2*j],   v0.x, a0);
                b0 = ffma2(gd[2*j+1], v0.y, b0);
                a1 = ffma2(gd[2*j],   v1.x, a1);
                b1 = ffma2(gd[2*j+1], v1.y, b1);
            }
            float sc0, sc1, sc2, sc3;
            unpack2(fadd2(a0, b0), sc0, sc1);
            unpack2(fadd2(a1, b1), sc2, sc3);
            float m = fmaxf(fmaxf(sc0, sc1), fmaxf(sc2, sc3));
            if (m > best) { best = m; gbase = t * TILE_CW + 2 * p; }
        }
    }

    // Exact recompute of the winning group of 4 -> first index matching best.
    int bidx = gbase;
    {
        float g[DS];
        const float4* w4 = (const float4*)W;
        #pragma unroll
        for (int q = 0; q < 4; ++q) {
            float4 v = w4[q];
            g[4*q+0] = v.x * inv; g[4*q+1] = v.y * inv;
            g[4*q+2] = v.z * inv; g[4*q+3] = v.w * inv;
        }
        #pragma unroll
        for (int e = 3; e >= 0; --e) {
            const float* row = cb + (size_t)(gbase + e) * DS;
            float sc = score_of(g, row, bias_of(row));
            if (sc == best) bidx = gbase + e;
        }
    }

    // Dequantize + rescale
    float cw[DS];
    {
        const float4* c4 = (const float4*)(cb + (size_t)bidx * DS);
        #pragma unroll
        for (int q = 0; q < 4; ++q) {
            float4 v = c4[q];
            cw[4*q+0] = v.x * rsv; cw[4*q+1] = v.y * rsv;
            cw[4*q+2] = v.z * rsv; cw[4*q+3] = v.w * rsv;
        }
    }

    // ---- split-bf16 staging (plain row-major, k contiguous) ----
    if (s < SUBS_U) {
        // A row m, k in [kk0, kk0+16): hi@k, lo@64+k, hi@128+k
        const int m   = s >> 2;
        const int kk0 = (s & 3) << 4;
        unsigned short* rowp = g_Aext + (size_t)m * KE;
        #pragma unroll
        for (int e = 0; e < 8; ++e) {
            const int k = kk0 + 2 * e;
            float x0 = cw[2*e], x1 = cw[2*e+1];
            __nv_bfloat16 h0 = __float2bfloat16(x0);
            __nv_bfloat16 h1 = __float2bfloat16(x1);
            __nv_bfloat16 l0 = __float2bfloat16(x0 - __bfloat162float(h0));
            __nv_bfloat16 l1 = __float2bfloat16(x1 - __bfloat162float(h1));
            unsigned hp = (unsigned)__bfloat16_as_ushort(h0)
                        | ((unsigned)__bfloat16_as_ushort(h1) << 16);
            unsigned lp = (unsigned)__bfloat16_as_ushort(l0)
                        | ((unsigned)__bfloat16_as_ushort(l1) << 16);
            *(unsigned*)(rowp + k)        = hp;
            *(unsigned*)(rowp + 64 + k)   = lp;
            *(unsigned*)(rowp + 128 + k)  = hp;
        }
    } else {
        // B operand row n (= output col), col kB: hi@kB, hi@64+kB, lo@128+kB
        const int kB  = s2 >> 8;
        const int n0g = (s2 & 255) << 4;
        #pragma unroll
        for (int i = 0; i < DS; ++i) {
            unsigned short* rowp = g_Bext + (size_t)(n0g + i) * KE;
            float x = cw[i];
            __nv_bfloat16 h = __float2bfloat16(x);
            __nv_bfloat16 l = __float2bfloat16(x - __bfloat162float(h));
            rowp[kB]        = __bfloat16_as_ushort(h);
            rowp[64 + kB]   = __bfloat16_as_ushort(h);
            rowp[128 + kB]  = __bfloat16_as_ushort(l);
        }
    }
}

// ---------------------------------------------------------------------------
// Kernel 2: HMMA GEMM (mma.sync m16n8k16 bf16 — base sm_103 target, no 'a').
// CTA tile 128x128, K=192. 8 warps as 2(m) x 4(n); warp tile 64x32.
// smem rows pitched 400 B -> ldmatrix conflict-free. 100 KB smem, 2 CTA/SM.
// ---------------------------------------------------------------------------
#define P_BY 400                      // smem row pitch in bytes (192*2=384 data)
#define A_SM_BYTES (128 * P_BY)       // 51200
#define GEMM_SMEM  (2 * A_SM_BYTES)   // 102400

__device__ __forceinline__ uint32_t smem_u32(const void* p) {
    uint32_t a;
    asm("{ .reg .u64 t; cvta.to.shared.u64 t, %1; cvt.u32.u64 %0, t; }"
        : "=r"(a) : "l"(p));
    return a;
}
__device__ __forceinline__ void ldsm4(uint32_t& r0, uint32_t& r1,
                                      uint32_t& r2, uint32_t& r3, uint32_t addr) {
    asm volatile("ldmatrix.sync.aligned.m8n8.x4.shared.b16 {%0,%1,%2,%3}, [%4];"
                 : "=r"(r0), "=r"(r1), "=r"(r2), "=r"(r3) : "r"(addr));
}
__device__ __forceinline__ void mma16816(float* c, const uint32_t* a,
                                         uint32_t b0, uint32_t b1) {
    asm("mma.sync.aligned.m16n8k16.row.col.f32.bf16.bf16.f32 "
        "{%0,%1,%2,%3}, {%4,%5,%6,%7}, {%8,%9}, {%0,%1,%2,%3};"
        : "+f"(c[0]), "+f"(c[1]), "+f"(c[2]), "+f"(c[3])
        : "r"(a[0]), "r"(a[1]), "r"(a[2]), "r"(a[3]), "r"(b0), "r"(b1));
}

__global__ __launch_bounds__(256) void gemm_mma_kernel(float* __restrict__ out)
{
    extern __shared__ __align__(16) unsigned char smem[];
    const int tid  = threadIdx.x;
    const int wid  = tid >> 5;
    const int lane = tid & 31;
    const int nb = blockIdx.x, mb = blockIdx.y;

    // ---- stage tiles: 128 rows x 24 uint4, pitch 400 B ----
    {
        const uint4* gA = (const uint4*)(g_Aext + (size_t)mb * 128 * KE);
        const uint4* gB = (const uint4*)(g_Bext + (size_t)nb * 128 * KE);
        #pragma unroll
        for (int it = 0; it < 12; ++it) {
            const int idx = tid + it * 256;      // 0..3071
            const int r = idx / 24, j = idx % 24;
            *(uint4*)(smem + r * P_BY + j * 16)              = gA[idx];
            *(uint4*)(smem + A_SM_BYTES + r * P_BY + j * 16) = gB[idx];
        }
    }
    __syncthreads();

    const uint32_t sbase = smem_u32(smem);
    const int wm = wid >> 2;          // 0..1  (64 rows)
    const int wn = wid & 3;           // 0..3  (32 cols)

    // ldmatrix lane address pieces
    const int aRow = lane & 15;
    const int aKof = (lane >> 4) * 16;
    const int g8   = lane >> 3;
    const int bRow = ((g8 & 2) ? 8 : 0) + (lane & 7);
    const int bKof = (g8 & 1) * 16;

    const uint32_t aAddr = sbase + (uint32_t)((wm * 64 + aRow) * P_BY + aKof);
    const uint32_t bAddr = sbase + A_SM_BYTES
                         + (uint32_t)((wn * 32 + bRow) * P_BY + bKof);

    float acc[4][4][4];
    #pragma unroll
    for (int i = 0; i < 4; ++i)
        #pragma unroll
        for (int j = 0; j < 4; ++j)
            #pragma unroll
            for (int e = 0; e < 4; ++e) acc[i][j][e] = 0.0f;

    #pragma unroll
    for (int ks = 0; ks < 12; ++ks) {
        const uint32_t kb = ks * 32;
        uint32_t a[4][4], b[2][4];
        #pragma unroll
        for (int mt = 0; mt < 4; ++mt)
            ldsm4(a[mt][0], a[mt][1], a[mt][2], a[mt][3],
                  aAddr + mt * 16 * P_BY + kb);
        #pragma unroll
        for (int bt = 0; bt < 2; ++bt)
            ldsm4(b[bt][0], b[bt][1], b[bt][2], b[bt][3],
                  bAddr + bt * 16 * P_BY + kb);
        #pragma unroll
        for (int mt = 0; mt < 4; ++mt)
            #pragma unroll
            for (int nt = 0; nt < 4; ++nt)
                mma16816(acc[mt][nt], a[mt],
                         b[nt >> 1][(nt & 1) * 2], b[nt >> 1][(nt & 1) * 2 + 1]);
    }

    // ---- epilogue: direct STG.64 per (row, col-pair) ----
    const int r   = lane >> 2;
    const int cp  = (lane & 3) * 2;
    float* obase = out + (size_t)(mb * 128 + wm * 64) * N_COLS_B
                 + nb * 128 + wn * 32;
    #pragma unroll
    for (int mt = 0; mt < 4; ++mt) {
        #pragma unroll
        for (int nt = 0; nt < 4; ++nt) {
            float* o0 = obase + (size_t)(mt * 16 + r) * N_COLS_B + nt * 8 + cp;
            *(float2*)o0                         = make_float2(acc[mt][nt][0], acc[mt][nt][1]);
            *(float2*)(o0 + 8 * N_COLS_B)        = make_float2(acc[mt][nt][2], acc[mt][nt][3]);
        }
    }
}

// ---------------------------------------------------------------------------
// Launch
// ---------------------------------------------------------------------------
extern "C" void kernel_launch(void* const* d_in, const int* in_sizes, int n_in,
                              void* d_out, int out_size)
{
    const float *U = nullptr, *B = nullptr, *rsU = nullptr, *rsB = nullptr, *cb = nullptr;
    for (int i = 0; i < n_in; ++i) {
        switch (in_sizes[i]) {
            case N_ROWS_U * RANK:  U   = (const float*)d_in[i]; break;
            case RANK * N_COLS_B:  B   = (const float*)d_in[i]; break;
            case N_ROWS_U:         rsU = (const float*)d_in[i]; break;
            case RANK:             rsB = (const float*)d_in[i]; break;
            case KCB * DS:         cb  = (const float*)d_in[i]; break;
            default: break;
        }
    }
    if (!U || !B || !rsU || !rsB || !cb) {
        U   = (const float*)d_in[0];
        B   = (const float*)d_in[1];
        rsU = (const float*)d_in[2];
        rsB = (const float*)d_in[3];
        cb  = (const float*)d_in[4];
    }

    cudaFuncSetAttribute(gemm_mma_kernel,
                         cudaFuncAttributeMaxDynamicSharedMemorySize, GEMM_SMEM);

    quant_kernel<<<TOTAL_SUBS / 128, 128>>>(U, B, rsU, rsB, cb);
    gemm_mma_kernel<<<dim3(N_COLS_B / 128, N_ROWS_U / 128), 256, GEMM_SMEM>>>((float*)d_out);
}

// round 8
// speedup vs baseline: 1.1233x; 1.0267x over previous
#include <cuda_runtime.h>
#include <cuda_bf16.h>
#include <cstdint>

// ---------------------------------------------------------------------------
// Problem shapes (fixed)
// ---------------------------------------------------------------------------
#define N_ROWS_U 16384
#define RANK     64
#define N_COLS_B 4096
#define KCB      2048
#define DS       16
#define SUBS_U   (N_ROWS_U * RANK / DS)   // 65536
#define SUBS_B   (RANK * N_COLS_B / DS)   // 16384
#define TOTAL_SUBS (SUBS_U + SUBS_B)      // 81920
#define TILE_CW   512
#define TILE_PAIR 256

// Split-bf16 K-concat: K_ext = 192 = [hi | lo | hi]_A  x  [hi | hi | lo]_B
#define KE 192

__device__ __align__(16) unsigned short g_Aext[(size_t)N_ROWS_U * KE]; // 6.3 MB
__device__ __align__(16) unsigned short g_Bext[(size_t)N_COLS_B * KE]; // 1.6 MB

typedef unsigned long long u64t;

// ---------------------------------------------------------------------------
// Packed f32x2 helpers
// ---------------------------------------------------------------------------
__device__ __forceinline__ u64t pack2(float a, float b) {
    u64t r;
    asm("mov.b64 %0, {%1, %2};" : "=l"(r)
        : "r"(__float_as_uint(a)), "r"(__float_as_uint(b)));
    return r;
}
__device__ __forceinline__ void unpack2(u64t v, float& a, float& b) {
    unsigned lo, hi;
    asm("mov.b64 {%0, %1}, %2;" : "=r"(lo), "=r"(hi) : "l"(v));
    a = __uint_as_float(lo);
    b = __uint_as_float(hi);
}
__device__ __forceinline__ u64t ffma2(u64t a, u64t b, u64t c) {
    u64t d;
    asm("fma.rn.f32x2 %0, %1, %2, %3;" : "=l"(d) : "l"(a), "l"(b), "l"(c));
    return d;
}
__device__ __forceinline__ u64t fadd2(u64t a, u64t b) {
    u64t d;
    asm("add.rn.f32x2 %0, %1, %2;" : "=l"(d) : "l"(a), "l"(b));
    return d;
}

// Strict fma chains, bitwise-reproducible (exact argmax recompute relies on it)
__device__ __forceinline__ float bias_of(const float* row) {
    float n = row[0] * row[0];
    #pragma unroll
    for (int i = 1; i < DS; ++i) n = fmaf(row[i], row[i], n);
    return -0.5f * n;
}
__device__ __forceinline__ float score_of(const float* g, const float* row, float bias) {
    float A = bias, B = 0.0f;
    #pragma unroll
    for (int j = 0; j < 8; ++j) {
        A = fmaf(g[2 * j],     row[2 * j],     A);
        B = fmaf(g[2 * j + 1], row[2 * j + 1], B);
    }
    return A + B;
}

// ---------------------------------------------------------------------------
// Kernel 1: PQ quantization. 640 CTAs x 64 threads x 2 subvectors = 81920.
// Each codeword-pair LDS feeds both subvectors -> fma-pipe-bound inner loop.
// Scoring chains bitwise-identical to prior passing rounds.
// ---------------------------------------------------------------------------
__global__ __launch_bounds__(64) void quant_kernel(
    const float* __restrict__ U, const float* __restrict__ Bm,
    const float* __restrict__ rsU, const float* __restrict__ rsB,
    const float* __restrict__ cb)
{
    __shared__ __align__(16) float s_cb[TILE_PAIR * 2 * DS];   // 32 KB
    __shared__ __align__(16) float s_bias[TILE_CW];            // 2 KB

    const int tid  = threadIdx.x;
    const int base = blockIdx.x * 128;          // 128 subvecs per block
    // SUBS_U = 65536 = 512*128 -> every block is entirely U-side or B-side.
    const bool isU = (base < SUBS_U);

    int   ss[2];
    float rsv[2], inv[2];
    const float* W[2];
    u64t gd[2][DS];

    ss[0] = base + tid;
    ss[1] = base + 64 + tid;
    #pragma unroll
    for (int v = 0; v < 2; ++v) {
        if (isU) {
            W[v]   = U + (size_t)ss[v] * DS;
            rsv[v] = rsU[ss[v] >> 2];
        } else {
            const int s2 = ss[v] - SUBS_U;
            W[v]   = Bm + (size_t)s2 * DS;
            rsv[v] = rsB[s2 >> 8];
        }
        inv[v] = 1.0f / rsv[v];
        const float4* w4 = (const float4*)W[v];
        #pragma unroll
        for (int q = 0; q < 4; ++q) {
            float4 w = w4[q];
            float g0 = w.x * inv[v], g1 = w.y * inv[v];
            float g2 = w.z * inv[v], g3 = w.w * inv[v];
            gd[v][4*q+0] = pack2(g0, g0);
            gd[v][4*q+1] = pack2(g1, g1);
            gd[v][4*q+2] = pack2(g2, g2);
            gd[v][4*q+3] = pack2(g3, g3);
        }
    }

    float best[2] = {-3.402823466e38f, -3.402823466e38f};
    int   gb[2]   = {0, 0};

    for (int t = 0; t < KCB / TILE_CW; ++t) {
        __syncthreads();
        for (int c = tid; c < TILE_CW; c += 64)
            s_bias[c] = bias_of(cb + (size_t)(t * TILE_CW + c) * DS);
        {
            const int h  = tid & 1;
            const int ii = (tid >> 1) & 15;
            const int grp = tid >> 5;           // 0..1
            for (int p = grp; p < TILE_PAIR; p += 2)
                s_cb[p * 32 + 2 * ii + h] =
                    cb[(size_t)(t * TILE_CW + 2 * p + h) * DS + ii];
        }
        __syncthreads();

        #pragma unroll 2
        for (int p = 0; p < TILE_PAIR; ++p) {
            const ulonglong2* q = (const ulonglong2*)(s_cb + p * 32);
            const u64t bias = *(const u64t*)(s_bias + 2 * p);
            u64t a0 = bias, b0 = 0ull;     // subvec 0
            u64t a1 = bias, b1 = 0ull;     // subvec 1
            #pragma unroll
            for (int j = 0; j < 8; ++j) {
                ulonglong2 v = q[j];
                a0 = ffma2(gd[0][2*j],   v.x, a0);
                b0 = ffma2(gd[0][2*j+1], v.y, b0);
                a1 = ffma2(gd[1][2*j],   v.x, a1);
                b1 = ffma2(gd[1][2*j+1], v.y, b1);
            }
            const int pb = t * TILE_CW + 2 * p;
            float sa, sb;
            unpack2(fadd2(a0, b0), sa, sb);
            float m0 = fmaxf(sa, sb);
            if (m0 > best[0]) { best[0] = m0; gb[0] = pb; }
            unpack2(fadd2(a1, b1), sa, sb);
            float m1 = fmaxf(sa, sb);
            if (m1 > best[1]) { best[1] = m1; gb[1] = pb; }
        }
    }

    // ---- per subvector: exact recompute of winning pair, dequant, staging ----
    #pragma unroll
    for (int v = 0; v < 2; ++v) {
        float g[DS];
        const float4* w4 = (const float4*)W[v];
        #pragma unroll
        for (int q = 0; q < 4; ++q) {
            float4 w = w4[q];
            g[4*q+0] = w.x * inv[v]; g[4*q+1] = w.y * inv[v];
            g[4*q+2] = w.z * inv[v]; g[4*q+3] = w.w * inv[v];
        }
        int bidx = gb[v];
        #pragma unroll
        for (int e = 1; e >= 0; --e) {
            const float* row = cb + (size_t)(gb[v] + e) * DS;
            float sc = score_of(g, row, bias_of(row));
            if (sc == best[v]) bidx = gb[v] + e;
        }

        float cw[DS];
        {
            const float4* c4 = (const float4*)(cb + (size_t)bidx * DS);
            #pragma unroll
            for (int q = 0; q < 4; ++q) {
                float4 w = c4[q];
                cw[4*q+0] = w.x * rsv[v]; cw[4*q+1] = w.y * rsv[v];
                cw[4*q+2] = w.z * rsv[v]; cw[4*q+3] = w.w * rsv[v];
            }
        }

        if (isU) {
            const int m   = ss[v] >> 2;
            const int kk0 = (ss[v] & 3) << 4;
            unsigned short* rowp = g_Aext + (size_t)m * KE;
            #pragma unroll
            for (int e = 0; e < 8; ++e) {
                const int k = kk0 + 2 * e;
                float x0 = cw[2*e], x1 = cw[2*e+1];
                __nv_bfloat16 h0 = __float2bfloat16(x0);
                __nv_bfloat16 h1 = __float2bfloat16(x1);
                __nv_bfloat16 l0 = __float2bfloat16(x0 - __bfloat162float(h0));
                __nv_bfloat16 l1 = __float2bfloat16(x1 - __bfloat162float(h1));
                unsigned hp = (unsigned)__bfloat16_as_ushort(h0)
                            | ((unsigned)__bfloat16_as_ushort(h1) << 16);
                unsigned lp = (unsigned)__bfloat16_as_ushort(l0)
                            | ((unsigned)__bfloat16_as_ushort(l1) << 16);
                *(unsigned*)(rowp + k)       = hp;
                *(unsigned*)(rowp + 64 + k)  = lp;
                *(unsigned*)(rowp + 128 + k) = hp;
            }
        } else {
            const int s2  = ss[v] - SUBS_U;
            const int kB  = s2 >> 8;
            const int n0g = (s2 & 255) << 4;
            #pragma unroll
            for (int i = 0; i < DS; ++i) {
                unsigned short* rowp = g_Bext + (size_t)(n0g + i) * KE;
                float x = cw[i];
                __nv_bfloat16 h = __float2bfloat16(x);
                __nv_bfloat16 l = __float2bfloat16(x - __bfloat162float(h));
                rowp[kB]       = __bfloat16_as_ushort(h);
                rowp[64 + kB]  = __bfloat16_as_ushort(h);
                rowp[128 + kB] = __bfloat16_as_ushort(l);
            }
        }
    }
}

// ---------------------------------------------------------------------------
// Kernel 2: HMMA GEMM (mma.sync m16n8k16 bf16, base sm_103 target).
// CTA tile 128x128, K=192. 4 warps as 2(m) x 2(n); warp tile 64x64.
// 8 LDSM per 32 MMAs (was 6 per 16). smem pitch 400 B, 100 KB, 2 CTA/SM.
// ---------------------------------------------------------------------------
#define P_BY 400
#define A_SM_BYTES (128 * P_BY)       // 51200
#define GEMM_SMEM  (2 * A_SM_BYTES)   // 102400

__device__ __forceinline__ uint32_t smem_u32(const void* p) {
    uint32_t a;
    asm("{ .reg .u64 t; cvta.to.shared.u64 t, %1; cvt.u32.u64 %0, t; }"
        : "=r"(a) : "l"(p));
    return a;
}
__device__ __forceinline__ void ldsm4(uint32_t& r0, uint32_t& r1,
                                      uint32_t& r2, uint32_t& r3, uint32_t addr) {
    asm volatile("ldmatrix.sync.aligned.m8n8.x4.shared.b16 {%0,%1,%2,%3}, [%4];"
                 : "=r"(r0), "=r"(r1), "=r"(r2), "=r"(r3) : "r"(addr));
}
__device__ __forceinline__ void mma16816(float* c, const uint32_t* a,
                                         uint32_t b0, uint32_t b1) {
    asm("mma.sync.aligned.m16n8k16.row.col.f32.bf16.bf16.f32 "
        "{%0,%1,%2,%3}, {%4,%5,%6,%7}, {%8,%9}, {%0,%1,%2,%3};"
        : "+f"(c[0]), "+f"(c[1]), "+f"(c[2]), "+f"(c[3])
        : "r"(a[0]), "r"(a[1]), "r"(a[2]), "r"(a[3]), "r"(b0), "r"(b1));
}

__global__ __launch_bounds__(128) void gemm_mma_kernel(float* __restrict__ out)
{
    extern __shared__ __align__(16) unsigned char smem[];
    const int tid  = threadIdx.x;
    const int wid  = tid >> 5;
    const int lane = tid & 31;
    const int nb = blockIdx.x, mb = blockIdx.y;

    // ---- stage tiles: 128 rows x 24 uint4 per operand, pitch 400 B ----
    {
        const uint4* gA = (const uint4*)(g_Aext + (size_t)mb * 128 * KE);
        const uint4* gB = (const uint4*)(g_Bext + (size_t)nb * 128 * KE);
        #pragma unroll
        for (int it = 0; it < 24; ++it) {
            const int idx = tid + it * 128;      // 0..3071
            const int r = idx / 24, j = idx % 24;
            *(uint4*)(smem + r * P_BY + j * 16)              = gA[idx];
            *(uint4*)(smem + A_SM_BYTES + r * P_BY + j * 16) = gB[idx];
        }
    }
    __syncthreads();

    const uint32_t sbase = smem_u32(smem);
    const int wm = wid >> 1;          // 0..1  (64 rows)
    const int wn = wid & 1;           // 0..1  (64 cols)

    const int aRow = lane & 15;
    const int aKof = (lane >> 4) * 16;
    const int g8   = lane >> 3;
    const int bRow = ((g8 & 2) ? 8 : 0) + (lane & 7);
    const int bKof = (g8 & 1) * 16;

    const uint32_t aAddr = sbase + (uint32_t)((wm * 64 + aRow) * P_BY + aKof);
    const uint32_t bAddr = sbase + A_SM_BYTES
                         + (uint32_t)((wn * 64 + bRow) * P_BY + bKof);

    float acc[4][8][4];
    #pragma unroll
    for (int i = 0; i < 4; ++i)
        #pragma unroll
        for (int j = 0; j < 8; ++j)
            #pragma unroll
            for (int e = 0; e < 4; ++e) acc[i][j][e] = 0.0f;

    #pragma unroll
    for (int ks = 0; ks < 12; ++ks) {
        const uint32_t kb = ks * 32;             // 16 elements * 2 B
        uint32_t a[4][4], b[4][4];
        #pragma unroll
        for (int mt = 0; mt < 4; ++mt)
            ldsm4(a[mt][0], a[mt][1], a[mt][2], a[mt][3],
                  aAddr + mt * 16 * P_BY + kb);
        #pragma unroll
        for (int bt = 0; bt < 4; ++bt)
            ldsm4(b[bt][0], b[bt][1], b[bt][2], b[bt][3],
                  bAddr + bt * 16 * P_BY + kb);
        #pragma unroll
        for (int mt = 0; mt < 4; ++mt)
            #pragma unroll
            for (int nt = 0; nt < 8; ++nt)
                mma16816(acc[mt][nt], a[mt],
                         b[nt >> 1][(nt & 1) * 2], b[nt >> 1][(nt & 1) * 2 + 1]);
    }

    // ---- epilogue: STG.64 per (row, col-pair) ----
    const int r  = lane >> 2;
    const int cp = (lane & 3) * 2;
    float* obase = out + (size_t)(mb * 128 + wm * 64) * N_COLS_B
                 + nb * 128 + wn * 64;
    #pragma unroll
    for (int mt = 0; mt < 4; ++mt) {
        #pragma unroll
        for (int nt = 0; nt < 8; ++nt) {
            float* o0 = obase + (size_t)(mt * 16 + r) * N_COLS_B + nt * 8 + cp;
            *(float2*)o0                  = make_float2(acc[mt][nt][0], acc[mt][nt][1]);
            *(float2*)(o0 + 8 * N_COLS_B) = make_float2(acc[mt][nt][2], acc[mt][nt][3]);
        }
    }
}

// ---------------------------------------------------------------------------
// Launch
// ---------------------------------------------------------------------------
extern "C" void kernel_launch(void* const* d_in, const int* in_sizes, int n_in,
                              void* d_out, int out_size)
{
    const float *U = nullptr, *B = nullptr, *rsU = nullptr, *rsB = nullptr, *cb = nullptr;
    for (int i = 0; i < n_in; ++i) {
        switch (in_sizes[i]) {
            case N_ROWS_U * RANK:  U   = (const float*)d_in[i]; break;
            case RANK * N_COLS_B:  B   = (const float*)d_in[i]; break;
            case N_ROWS_U:         rsU = (const float*)d_in[i]; break;
            case RANK:             rsB = (const float*)d_in[i]; break;
            case KCB * DS:         cb  = (const float*)d_in[i]; break;
            default: break;
        }
    }
    if (!U || !B || !rsU || !rsB || !cb) {
        U   = (const float*)d_in[0];
        B   = (const float*)d_in[1];
        rsU = (const float*)d_in[2];
        rsB = (const float*)d_in[3];
        cb  = (const float*)d_in[4];
    }

    cudaFuncSetAttribute(gemm_mma_kernel,
                         cudaFuncAttributeMaxDynamicSharedMemorySize, GEMM_SMEM);

    quant_kernel<<<TOTAL_SUBS / 128, 64>>>(U, B, rsU, rsB, cb);
    gemm_mma_kernel<<<dim3(N_COLS_B / 128, N_ROWS_U / 128), 128, GEMM_SMEM>>>((float*)d_out);
}

// round 9
// speedup vs baseline: 1.1264x; 1.0027x over previous
#include <cuda_runtime.h>
#include <cuda_bf16.h>
#include <cstdint>

// ---------------------------------------------------------------------------
// Problem shapes (fixed)
// ---------------------------------------------------------------------------
#define N_ROWS_U 16384
#define RANK     64
#define N_COLS_B 4096
#define KCB      2048
#define DS       16
#define SUBS_U   (N_ROWS_U * RANK / DS)   // 65536
#define SUBS_B   (RANK * N_COLS_B / DS)   // 16384
#define TOTAL_SUBS (SUBS_U + SUBS_B)      // 81920
#define TILE_CW   512
#define TILE_PAIR 256

// Split-bf16 K-concat: K_ext = 192 = [hi | lo | hi]_A  x  [hi | hi | lo]_B
#define KE 192

__device__ __align__(16) unsigned short g_Aext[(size_t)N_ROWS_U * KE]; // 6.3 MB
__device__ __align__(16) unsigned short g_Bext[(size_t)N_COLS_B * KE]; // 1.6 MB

typedef unsigned long long u64t;

// ---------------------------------------------------------------------------
// Packed f32x2 helpers
// ---------------------------------------------------------------------------
__device__ __forceinline__ u64t pack2(float a, float b) {
    u64t r;
    asm("mov.b64 %0, {%1, %2};" : "=l"(r)
        : "r"(__float_as_uint(a)), "r"(__float_as_uint(b)));
    return r;
}
__device__ __forceinline__ void unpack2(u64t v, float& a, float& b) {
    unsigned lo, hi;
    asm("mov.b64 {%0, %1}, %2;" : "=r"(lo), "=r"(hi) : "l"(v));
    a = __uint_as_float(lo);
    b = __uint_as_float(hi);
}
__device__ __forceinline__ u64t ffma2(u64t a, u64t b, u64t c) {
    u64t d;
    asm("fma.rn.f32x2 %0, %1, %2, %3;" : "=l"(d) : "l"(a), "l"(b), "l"(c));
    return d;
}
__device__ __forceinline__ u64t fadd2(u64t a, u64t b) {
    u64t d;
    asm("add.rn.f32x2 %0, %1, %2;" : "=l"(d) : "l"(a), "l"(b));
    return d;
}

// Strict fma chains, bitwise-reproducible (exact argmax recompute relies on it)
__device__ __forceinline__ float bias_of(const float* row) {
    float n = row[0] * row[0];
    #pragma unroll
    for (int i = 1; i < DS; ++i) n = fmaf(row[i], row[i], n);
    return -0.5f * n;
}
__device__ __forceinline__ float score_of(const float* g, const float* row, float bias) {
    float A = bias, B = 0.0f;
    #pragma unroll
    for (int j = 0; j < 8; ++j) {
        A = fmaf(g[2 * j],     row[2 * j],     A);
        B = fmaf(g[2 * j + 1], row[2 * j + 1], B);
    }
    return A + B;
}

// ---------------------------------------------------------------------------
// Kernel 1: PQ quantization. 640 CTAs x 64 threads x 2 subvectors = 81920.
// Each codeword-pair LDS feeds both subvectors -> fma-pipe-bound inner loop.
// Scoring chains bitwise-identical to prior passing rounds.
// ---------------------------------------------------------------------------
__global__ __launch_bounds__(64) void quant_kernel(
    const float* __restrict__ U, const float* __restrict__ Bm,
    const float* __restrict__ rsU, const float* __restrict__ rsB,
    const float* __restrict__ cb)
{
    __shared__ __align__(16) float s_cb[TILE_PAIR * 2 * DS];   // 32 KB
    __shared__ __align__(16) float s_bias[TILE_CW];            // 2 KB

    const int tid  = threadIdx.x;
    const int base = blockIdx.x * 128;          // 128 subvecs per block
    // SUBS_U = 65536 = 512*128 -> every block is entirely U-side or B-side.
    const bool isU = (base < SUBS_U);

    int   ss[2];
    float rsv[2], inv[2];
    const float* W[2];
    u64t gd[2][DS];

    ss[0] = base + tid;
    ss[1] = base + 64 + tid;
    #pragma unroll
    for (int v = 0; v < 2; ++v) {
        if (isU) {
            W[v]   = U + (size_t)ss[v] * DS;
            rsv[v] = rsU[ss[v] >> 2];
        } else {
            const int s2 = ss[v] - SUBS_U;
            W[v]   = Bm + (size_t)s2 * DS;
            rsv[v] = rsB[s2 >> 8];
        }
        inv[v] = 1.0f / rsv[v];
        const float4* w4 = (const float4*)W[v];
        #pragma unroll
        for (int q = 0; q < 4; ++q) {
            float4 w = w4[q];
            float g0 = w.x * inv[v], g1 = w.y * inv[v];
            float g2 = w.z * inv[v], g3 = w.w * inv[v];
            gd[v][4*q+0] = pack2(g0, g0);
            gd[v][4*q+1] = pack2(g1, g1);
            gd[v][4*q+2] = pack2(g2, g2);
            gd[v][4*q+3] = pack2(g3, g3);
        }
    }

    float best[2] = {-3.402823466e38f, -3.402823466e38f};
    int   gb[2]   = {0, 0};

    for (int t = 0; t < KCB / TILE_CW; ++t) {
        __syncthreads();
        for (int c = tid; c < TILE_CW; c += 64)
            s_bias[c] = bias_of(cb + (size_t)(t * TILE_CW + c) * DS);
        {
            const int h  = tid & 1;
            const int ii = (tid >> 1) & 15;
            const int grp = tid >> 5;           // 0..1
            for (int p = grp; p < TILE_PAIR; p += 2)
                s_cb[p * 32 + 2 * ii + h] =
                    cb[(size_t)(t * TILE_CW + 2 * p + h) * DS + ii];
        }
        __syncthreads();

        #pragma unroll 2
        for (int p = 0; p < TILE_PAIR; ++p) {
            const ulonglong2* q = (const ulonglong2*)(s_cb + p * 32);
            const u64t bias = *(const u64t*)(s_bias + 2 * p);
            u64t a0 = bias, b0 = 0ull;     // subvec 0
            u64t a1 = bias, b1 = 0ull;     // subvec 1
            #pragma unroll
            for (int j = 0; j < 8; ++j) {
                ulonglong2 v = q[j];
                a0 = ffma2(gd[0][2*j],   v.x, a0);
                b0 = ffma2(gd[0][2*j+1], v.y, b0);
                a1 = ffma2(gd[1][2*j],   v.x, a1);
                b1 = ffma2(gd[1][2*j+1], v.y, b1);
            }
            const int pb = t * TILE_CW + 2 * p;
            float sa, sb;
            unpack2(fadd2(a0, b0), sa, sb);
            float m0 = fmaxf(sa, sb);
            if (m0 > best[0]) { best[0] = m0; gb[0] = pb; }
            unpack2(fadd2(a1, b1), sa, sb);
            float m1 = fmaxf(sa, sb);
            if (m1 > best[1]) { best[1] = m1; gb[1] = pb; }
        }
    }

    // ---- per subvector: exact recompute of winning pair, dequant, staging ----
    #pragma unroll
    for (int v = 0; v < 2; ++v) {
        float g[DS];
        const float4* w4 = (const float4*)W[v];
        #pragma unroll
        for (int q = 0; q < 4; ++q) {
            float4 w = w4[q];
            g[4*q+0] = w.x * inv[v]; g[4*q+1] = w.y * inv[v];
            g[4*q+2] = w.z * inv[v]; g[4*q+3] = w.w * inv[v];
        }
        int bidx = gb[v];
        #pragma unroll
        for (int e = 1; e >= 0; --e) {
            const float* row = cb + (size_t)(gb[v] + e) * DS;
            float sc = score_of(g, row, bias_of(row));
            if (sc == best[v]) bidx = gb[v] + e;
        }

        float cw[DS];
        {
            const float4* c4 = (const float4*)(cb + (size_t)bidx * DS);
            #pragma unroll
            for (int q = 0; q < 4; ++q) {
                float4 w = c4[q];
                cw[4*q+0] = w.x * rsv[v]; cw[4*q+1] = w.y * rsv[v];
                cw[4*q+2] = w.z * rsv[v]; cw[4*q+3] = w.w * rsv[v];
            }
        }

        if (isU) {
            const int m   = ss[v] >> 2;
            const int kk0 = (ss[v] & 3) << 4;
            unsigned short* rowp = g_Aext + (size_t)m * KE;
            #pragma unroll
            for (int e = 0; e < 8; ++e) {
                const int k = kk0 + 2 * e;
                float x0 = cw[2*e], x1 = cw[2*e+1];
                __nv_bfloat16 h0 = __float2bfloat16(x0);
                __nv_bfloat16 h1 = __float2bfloat16(x1);
                __nv_bfloat16 l0 = __float2bfloat16(x0 - __bfloat162float(h0));
                __nv_bfloat16 l1 = __float2bfloat16(x1 - __bfloat162float(h1));
                unsigned hp = (unsigned)__bfloat16_as_ushort(h0)
                            | ((unsigned)__bfloat16_as_ushort(h1) << 16);
                unsigned lp = (unsigned)__bfloat16_as_ushort(l0)
                            | ((unsigned)__bfloat16_as_ushort(l1) << 16);
                *(unsigned*)(rowp + k)       = hp;
                *(unsigned*)(rowp + 64 + k)  = lp;
                *(unsigned*)(rowp + 128 + k) = hp;
            }
        } else {
            const int s2  = ss[v] - SUBS_U;
            const int kB  = s2 >> 8;
            const int n0g = (s2 & 255) << 4;
            #pragma unroll
            for (int i = 0; i < DS; ++i) {
                unsigned short* rowp = g_Bext + (size_t)(n0g + i) * KE;
                float x = cw[i];
                __nv_bfloat16 h = __float2bfloat16(x);
                __nv_bfloat16 l = __float2bfloat16(x - __bfloat162float(h));
                rowp[kB]       = __bfloat16_as_ushort(h);
                rowp[64 + kB]  = __bfloat16_as_ushort(h);
                rowp[128 + kB] = __bfloat16_as_ushort(l);
            }
        }
    }
}

// ---------------------------------------------------------------------------
// Kernel 2: HMMA GEMM (mma.sync m16n8k16 bf16, base sm_103 target).
// CTA tile 128x128, K=192. 4 warps as 2(m) x 2(n); warp tile 64x64.
// 8 LDSM per 32 MMAs (was 6 per 16). smem pitch 400 B, 100 KB, 2 CTA/SM.
// ---------------------------------------------------------------------------
#define P_BY 400
#define A_SM_BYTES (128 * P_BY)       // 51200
#define GEMM_SMEM  (2 * A_SM_BYTES)   // 102400

__device__ __forceinline__ uint32_t smem_u32(const void* p) {
    uint32_t a;
    asm("{ .reg .u64 t; cvta.to.shared.u64 t, %1; cvt.u32.u64 %0, t; }"
        : "=r"(a) : "l"(p));
    return a;
}
__device__ __forceinline__ void ldsm4(uint32_t& r0, uint32_t& r1,
                                      uint32_t& r2, uint32_t& r3, uint32_t addr) {
    asm volatile("ldmatrix.sync.aligned.m8n8.x4.shared.b16 {%0,%1,%2,%3}, [%4];"
                 : "=r"(r0), "=r"(r1), "=r"(r2), "=r"(r3) : "r"(addr));
}
__device__ __forceinline__ void mma16816(float* c, const uint32_t* a,
                                         uint32_t b0, uint32_t b1) {
    asm("mma.sync.aligned.m16n8k16.row.col.f32.bf16.bf16.f32 "
        "{%0,%1,%2,%3}, {%4,%5,%6,%7}, {%8,%9}, {%0,%1,%2,%3};"
        : "+f"(c[0]), "+f"(c[1]), "+f"(c[2]), "+f"(c[3])
        : "r"(a[0]), "r"(a[1]), "r"(a[2]), "r"(a[3]), "r"(b0), "r"(b1));
}

__global__ __launch_bounds__(128) void gemm_mma_kernel(float* __restrict__ out)
{
    extern __shared__ __align__(16) unsigned char smem[];
    const int tid  = threadIdx.x;
    const int wid  = tid >> 5;
    const int lane = tid & 31;
    const int nb = blockIdx.x, mb = blockIdx.y;

    // ---- stage tiles: 128 rows x 24 uint4 per operand, pitch 400 B ----
    {
        const uint4* gA = (const uint4*)(g_Aext + (size_t)mb * 128 * KE);
        const uint4* gB = (const uint4*)(g_Bext + (size_t)nb * 128 * KE);
        #pragma unroll
        for (int it = 0; it < 24; ++it) {
            const int idx = tid + it * 128;      // 0..3071
            const int r = idx / 24, j = idx % 24;
            *(uint4*)(smem + r * P_BY + j * 16)              = gA[idx];
            *(uint4*)(smem + A_SM_BYTES + r * P_BY + j * 16) = gB[idx];
        }
    }
    __syncthreads();

    const uint32_t sbase = smem_u32(smem);
    const int wm = wid >> 1;          // 0..1  (64 rows)
    const int wn = wid & 1;           // 0..1  (64 cols)

    const int aRow = lane & 15;
    const int aKof = (lane >> 4) * 16;
    const int g8   = lane >> 3;
    const int bRow = ((g8 & 2) ? 8 : 0) + (lane & 7);
    const int bKof = (g8 & 1) * 16;

    const uint32_t aAddr = sbase + (uint32_t)((wm * 64 + aRow) * P_BY + aKof);
    const uint32_t bAddr = sbase + A_SM_BYTES
                         + (uint32_t)((wn * 64 + bRow) * P_BY + bKof);

    float acc[4][8][4];
    #pragma unroll
    for (int i = 0; i < 4; ++i)
        #pragma unroll
        for (int j = 0; j < 8; ++j)
            #pragma unroll
            for (int e = 0; e < 4; ++e) acc[i][j][e] = 0.0f;

    #pragma unroll
    for (int ks = 0; ks < 12; ++ks) {
        const uint32_t kb = ks * 32;             // 16 elements * 2 B
        uint32_t a[4][4], b[4][4];
        #pragma unroll
        for (int mt = 0; mt < 4; ++mt)
            ldsm4(a[mt][0], a[mt][1], a[mt][2], a[mt][3],
                  aAddr + mt * 16 * P_BY + kb);
        #pragma unroll
        for (int bt = 0; bt < 4; ++bt)
            ldsm4(b[bt][0], b[bt][1], b[bt][2], b[bt][3],
                  bAddr + bt * 16 * P_BY + kb);
        #pragma unroll
        for (int mt = 0; mt < 4; ++mt)
            #pragma unroll
            for (int nt = 0; nt < 8; ++nt)
                mma16816(acc[mt][nt], a[mt],
                         b[nt >> 1][(nt & 1) * 2], b[nt >> 1][(nt & 1) * 2 + 1]);
    }

    // ---- epilogue: STG.64 per (row, col-pair) ----
    const int r  = lane >> 2;
    const int cp = (lane & 3) * 2;
    float* obase = out + (size_t)(mb * 128 + wm * 64) * N_COLS_B
                 + nb * 128 + wn * 64;
    #pragma unroll
    for (int mt = 0; mt < 4; ++mt) {
        #pragma unroll
        for (int nt = 0; nt < 8; ++nt) {
            float* o0 = obase + (size_t)(mt * 16 + r) * N_COLS_B + nt * 8 + cp;
            *(float2*)o0                  = make_float2(acc[mt][nt][0], acc[mt][nt][1]);
            *(float2*)(o0 + 8 * N_COLS_B) = make_float2(acc[mt][nt][2], acc[mt][nt][3]);
        }
    }
}

// ---------------------------------------------------------------------------
// Launch
// ---------------------------------------------------------------------------
extern "C" void kernel_launch(void* const* d_in, const int* in_sizes, int n_in,
                              void* d_out, int out_size)
{
    const float *U = nullptr, *B = nullptr, *rsU = nullptr, *rsB = nullptr, *cb = nullptr;
    for (int i = 0; i < n_in; ++i) {
        switch (in_sizes[i]) {
            case N_ROWS_U * RANK:  U   = (const float*)d_in[i]; break;
            case RANK * N_COLS_B:  B   = (const float*)d_in[i]; break;
            case N_ROWS_U:         rsU = (const float*)d_in[i]; break;
            case RANK:             rsB = (const float*)d_in[i]; break;
            case KCB * DS:         cb  = (const float*)d_in[i]; break;
            default: break;
        }
    }
    if (!U || !B || !rsU || !rsB || !cb) {
        U   = (const float*)d_in[0];
        B   = (const float*)d_in[1];
        rsU = (const float*)d_in[2];
        rsB = (const float*)d_in[3];
        cb  = (const float*)d_in[4];
    }

    cudaFuncSetAttribute(gemm_mma_kernel,
                         cudaFuncAttributeMaxDynamicSharedMemorySize, GEMM_SMEM);

    quant_kernel<<<TOTAL_SUBS / 128, 64>>>(U, B, rsU, rsB, cb);
    gemm_mma_kernel<<<dim3(N_COLS_B / 128, N_ROWS_U / 128), 128, GEMM_SMEM>>>((float*)d_out);
}

// round 12
// speedup vs baseline: 1.3912x; 1.2351x over previous
#include <cuda_runtime.h>
#include <cuda_bf16.h>
#include <cstdint>

#define N_ROWS_U 16384
#define RANK     64
#define N_COLS_B 4096
#define KCB      2048
#define DS       16
#define SUBS_U   65536
#define SUBS_B   16384
#define TOTAL_SUBS 81920
#define KE 192
#define QP 80                         // scoring C smem pitch (bytes)

__device__ __align__(16) unsigned short g_Aext[(size_t)N_ROWS_U * KE];
__device__ __align__(16) unsigned short g_Bext[(size_t)N_COLS_B * KE];
__device__ __align__(16) unsigned short g_Gext[(size_t)TOTAL_SUBS * 32];
__device__ __align__(16) unsigned short g_Cext[(size_t)KCB * 32];
__device__ float g_CbBias[KCB];

// ---- exact fp32 chains (selection depends on these; unchanged from R7-9) ----
__device__ __forceinline__ float bias_of(const float* row) {
    float n = row[0] * row[0];
    #pragma unroll
    for (int i = 1; i < DS; ++i) n = fmaf(row[i], row[i], n);
    return -0.5f * n;
}
__device__ __forceinline__ float score_of(const float* g, const float* row, float bias) {
    float A = bias, B = 0.0f;
    #pragma unroll
    for (int j = 0; j < 8; ++j) {
        A = fmaf(g[2 * j],     row[2 * j],     A);
        B = fmaf(g[2 * j + 1], row[2 * j + 1], B);
    }
    return A + B;
}
__device__ __noinline__ float exact_score(const float* W, float inv, const float* cbrow) {
    float g[DS];
    const float4* w4 = (const float4*)W;
    #pragma unroll
    for (int q = 0; q < 4; ++q) {
        float4 v = w4[q];
        g[4*q+0] = v.x * inv; g[4*q+1] = v.y * inv;
        g[4*q+2] = v.z * inv; g[4*q+3] = v.w * inv;
    }
    return score_of(g, cbrow, bias_of(cbrow));
}

__device__ __forceinline__ uint32_t smem_u32(const void* p) {
    uint32_t a;
    asm("{ .reg .u64 t; cvta.to.shared.u64 t, %1; cvt.u32.u64 %0, t; }"
        : "=r"(a) : "l"(p));
    return a;
}
__device__ __forceinline__ void ldsm4(uint32_t& r0, uint32_t& r1,
                                      uint32_t& r2, uint32_t& r3, uint32_t addr) {
    asm volatile("ldmatrix.sync.aligned.m8n8.x4.shared.b16 {%0,%1,%2,%3}, [%4];"
                 : "=r"(r0), "=r"(r1), "=r"(r2), "=r"(r3) : "r"(addr));
}
__device__ __forceinline__ void mma16816(float* c, const uint32_t* a,
                                         uint32_t b0, uint32_t b1) {
    asm("mma.sync.aligned.m16n8k16.row.col.f32.bf16.bf16.f32 "
        "{%0,%1,%2,%3}, {%4,%5,%6,%7}, {%8,%9}, {%0,%1,%2,%3};"
        : "+f"(c[0]), "+f"(c[1]), "+f"(c[2]), "+f"(c[3])
        : "r"(a[0]), "r"(a[1]), "r"(a[2]), "r"(a[3]), "r"(b0), "r"(b1));
}
__device__ __forceinline__ void mma16816z(float* c, const uint32_t* a,
                                          uint32_t b0, uint32_t b1) {
    float z = 0.0f;
    asm("mma.sync.aligned.m16n8k16.row.col.f32.bf16.bf16.f32 "
        "{%0,%1,%2,%3}, {%4,%5,%6,%7}, {%8,%9}, {%10,%11,%12,%13};"
        : "=f"(c[0]), "=f"(c[1]), "=f"(c[2]), "=f"(c[3])
        : "r"(a[0]), "r"(a[1]), "r"(a[2]), "r"(a[3]), "r"(b0), "r"(b1),
          "f"(z), "f"(z), "f"(z), "f"(z));
}

// ---- prep: codebook bf16 image [c_hi | c_hi] + fp32 bias ----
__global__ __launch_bounds__(128) void prep_cb(const float* __restrict__ cb) {
    const int c = blockIdx.x * 128 + threadIdx.x;
    float row[DS];
    const float4* r4 = (const float4*)(cb + (size_t)c * DS);
    #pragma unroll
    for (int q = 0; q < 4; ++q) {
        float4 v = r4[q];
        row[4*q] = v.x; row[4*q+1] = v.y; row[4*q+2] = v.z; row[4*q+3] = v.w;
    }
    g_CbBias[c] = bias_of(row);
    unsigned short* o = g_Cext + (size_t)c * 32;
    #pragma unroll
    for (int i = 0; i < DS; ++i) {
        unsigned short h = __bfloat16_as_ushort(__float2bfloat16(row[i]));
        o[i] = h; o[16 + i] = h;
    }
}

// ---- prep: subvector bf16 image [g_hi | g_lo] ----
__global__ __launch_bounds__(128) void prep_g(
    const float* __restrict__ U, const float* __restrict__ Bm,
    const float* __restrict__ rsU, const float* __restrict__ rsB)
{
    const int s = blockIdx.x * 128 + threadIdx.x;
    const float* W; float rsv;
    if (s < SUBS_U) { W = U + (size_t)s * DS; rsv = rsU[s >> 2]; }
    else { int s2 = s - SUBS_U; W = Bm + (size_t)s2 * DS; rsv = rsB[s2 >> 8]; }
    const float inv = 1.0f / rsv;
    unsigned short* o = g_Gext + (size_t)s * 32;
    const float4* w4 = (const float4*)W;
    #pragma unroll
    for (int q = 0; q < 4; ++q) {
        float4 v = w4[q];
        float gg[4] = {v.x * inv, v.y * inv, v.z * inv, v.w * inv};
        #pragma unroll
        for (int e = 0; e < 4; ++e) {
            __nv_bfloat16 hi = __float2bfloat16(gg[e]);
            __nv_bfloat16 lo = __float2bfloat16(gg[e] - __bfloat162float(hi));
            o[4*q + e]      = __bfloat16_as_ushort(hi);
            o[16 + 4*q + e] = __bfloat16_as_ushort(lo);
        }
    }
}

// ---- staging of one selected codeword into GEMM operands ----
__device__ __noinline__ void stage_row(int s, int bidx, float rsv,
                                       const float* __restrict__ cb) {
    float cw[DS];
    const float4* c4 = (const float4*)(cb + (size_t)bidx * DS);
    #pragma unroll
    for (int q = 0; q < 4; ++q) {
        float4 v = c4[q];
        cw[4*q+0] = v.x * rsv; cw[4*q+1] = v.y * rsv;
        cw[4*q+2] = v.z * rsv; cw[4*q+3] = v.w * rsv;
    }
    if (s < SUBS_U) {
        const int m = s >> 2, kk0 = (s & 3) << 4;
        unsigned short* rowp = g_Aext + (size_t)m * KE;
        #pragma unroll
        for (int e = 0; e < 8; ++e) {
            const int k = kk0 + 2 * e;
            float x0 = cw[2*e], x1 = cw[2*e+1];
            __nv_bfloat16 h0 = __float2bfloat16(x0), h1 = __float2bfloat16(x1);
            __nv_bfloat16 l0 = __float2bfloat16(x0 - __bfloat162float(h0));
            __nv_bfloat16 l1 = __float2bfloat16(x1 - __bfloat162float(h1));
            unsigned hp = (unsigned)__bfloat16_as_ushort(h0)
                        | ((unsigned)__bfloat16_as_ushort(h1) << 16);
            unsigned lp = (unsigned)__bfloat16_as_ushort(l0)
                        | ((unsigned)__bfloat16_as_ushort(l1) << 16);
            *(unsigned*)(rowp + k)       = hp;
            *(unsigned*)(rowp + 64 + k)  = lp;
            *(unsigned*)(rowp + 128 + k) = hp;
        }
    } else {
        const int s2 = s - SUBS_U, kB = s2 >> 8, n0g = (s2 & 255) << 4;
        #pragma unroll
        for (int i = 0; i < DS; ++i) {
            unsigned short* rowp = g_Bext + (size_t)(n0g + i) * KE;
            float x = cw[i];
            __nv_bfloat16 h = __float2bfloat16(x);
            __nv_bfloat16 l = __float2bfloat16(x - __bfloat162float(h));
            rowp[kB]       = __bfloat16_as_ushort(h);
            rowp[64 + kB]  = __bfloat16_as_ushort(h);
            rowp[128 + kB] = __bfloat16_as_ushort(l);
        }
    }
}

// ---- HMMA chunk: 64 codeword cols, K=32 (2 ksteps), acc[nt][4] fp32 ----
__device__ __forceinline__ void score_chunk(float acc[8][4], const uint32_t a[2][4],
                                            uint32_t sbase, int ch, int bRow, int bKof)
{
    #pragma unroll
    for (int ks = 0; ks < 2; ++ks) {
        uint32_t b[4][4];
        #pragma unroll
        for (int bt = 0; bt < 4; ++bt)
            ldsm4(b[bt][0], b[bt][1], b[bt][2], b[bt][3],
                  sbase + (uint32_t)((ch * 64 + bt * 16 + bRow) * QP + ks * 32 + bKof));
        #pragma unroll
        for (int nt = 0; nt < 8; ++nt) {
            if (ks == 0) mma16816z(acc[nt], a[0], b[nt>>1][(nt&1)*2], b[nt>>1][(nt&1)*2+1]);
            else         mma16816 (acc[nt], a[1], b[nt>>1][(nt&1)*2], b[nt>>1][(nt&1)*2+1]);
        }
    }
}

#define Q_SMEM (KCB * QP + KCB * 4)   // 172032

__global__ __launch_bounds__(384) void score_kernel(
    const float* __restrict__ U, const float* __restrict__ Bm,
    const float* __restrict__ rsU, const float* __restrict__ rsB,
    const float* __restrict__ cb)
{
    extern __shared__ __align__(16) unsigned char qsm[];
    float* sBias = (float*)(qsm + KCB * QP);
    const int tid = threadIdx.x, wid = tid >> 5, lane = tid & 31;

    {   // stage resident C + bias
        const uint4* src = (const uint4*)g_Cext;
        for (int idx = tid; idx < KCB * 4; idx += 384) {
            const int r = idx >> 2, j = idx & 3;
            *(uint4*)(qsm + r * QP + j * 16) = src[idx];
        }
        for (int c = tid; c < KCB; c += 384) sBias[c] = g_CbBias[c];
    }
    __syncthreads();

    const uint32_t sbase = smem_u32(qsm);
    const int g8 = lane >> 3;
    const int bRow = ((g8 & 2) ? 8 : 0) + (lane & 7);
    const int bKof = (g8 & 1) * 16;
    const int lr = lane & 3, cp = lr * 2;

    for (int unit = blockIdx.x * 12 + wid; unit < TOTAL_SUBS / 16; unit += 148 * 12) {
        const int s0 = unit * 16 + (lane >> 2), s1 = s0 + 8;

        // per-row context
        const float *W0, *W1; float rs0, rs1;
        if (s0 < SUBS_U) { W0 = U + (size_t)s0 * DS; rs0 = rsU[s0 >> 2]; }
        else { int t = s0 - SUBS_U; W0 = Bm + (size_t)t * DS; rs0 = rsB[t >> 8]; }
        if (s1 < SUBS_U) { W1 = U + (size_t)s1 * DS; rs1 = rsU[s1 >> 2]; }
        else { int t = s1 - SUBS_U; W1 = Bm + (size_t)t * DS; rs1 = rsB[t >> 8]; }
        const float in0 = 1.0f / rs0, in1 = 1.0f / rs1;

        float gn0 = 0.0f, gn1 = 0.0f;
        #pragma unroll
        for (int i = 0; i < DS; ++i) {
            float a0 = W0[i] * in0, a1 = W1[i] * in1;
            gn0 = fmaf(a0, a0, gn0); gn1 = fmaf(a1, a1, gn1);
        }
        const float tol0 = 1e-3f * sqrtf(gn0), tol1 = 1e-3f * sqrtf(gn1);

        // A frags from g_Gext (row-major 16 u32 per row)
        uint32_t a[2][4];
        {
            const unsigned* G = (const unsigned*)g_Gext;
            #pragma unroll
            for (int ks = 0; ks < 2; ++ks) {
                a[ks][0] = G[(size_t)s0 * 16 + ks * 8 + lr];
                a[ks][1] = G[(size_t)s1 * 16 + ks * 8 + lr];
                a[ks][2] = G[(size_t)s0 * 16 + ks * 8 + 4 + lr];
                a[ks][3] = G[(size_t)s1 * 16 + ks * 8 + 4 + lr];
            }
        }

        // ---- pass 1: row maxima ----
        float r0 = -3.402823466e38f, r1 = -3.402823466e38f;
        for (int ch = 0; ch < 32; ++ch) {
            float acc[8][4];
            score_chunk(acc, a, sbase, ch, bRow, bKof);
            #pragma unroll
            for (int nt = 0; nt < 8; ++nt) {
                float2 bp = *(const float2*)(sBias + ch * 64 + nt * 8 + cp);
                r0 = fmaxf(r0, fmaxf(acc[nt][0] + bp.x, acc[nt][1] + bp.y));
                r1 = fmaxf(r1, fmaxf(acc[nt][2] + bp.x, acc[nt][3] + bp.y));
            }
        }
        r0 = fmaxf(r0, __shfl_xor_sync(~0u, r0, 1));
        r0 = fmaxf(r0, __shfl_xor_sync(~0u, r0, 2));
        r1 = fmaxf(r1, __shfl_xor_sync(~0u, r1, 1));
        r1 = fmaxf(r1, __shfl_xor_sync(~0u, r1, 2));
        const float th0 = r0 - 2.0f * tol0, th1 = r1 - 2.0f * tol1;

        // ---- pass 2: recompute (bitwise identical), verify candidates ----
        float vb0 = -3.402823466e38f, vb1 = -3.402823466e38f;
        int vi0 = 1 << 30, vi1 = 1 << 30;
        for (int ch = 0; ch < 32; ++ch) {
            float acc[8][4];
            score_chunk(acc, a, sbase, ch, bRow, bKof);
            #pragma unroll
            for (int nt = 0; nt < 8; ++nt) {
                float2 bp = *(const float2*)(sBias + ch * 64 + nt * 8 + cp);
                const int cbase = ch * 64 + nt * 8 + cp;
                #pragma unroll
                for (int e = 0; e < 2; ++e) {
                    float bb = e ? bp.y : bp.x;
                    if (acc[nt][e] + bb >= th0) {
                        const int c = cbase + e;
                        float sc = exact_score(W0, in0, cb + (size_t)c * DS);
                        if (sc > vb0 || (sc == vb0 && c < vi0)) { vb0 = sc; vi0 = c; }
                    }
                    if (acc[nt][2 + e] + bb >= th1) {
                        const int c = cbase + e;
                        float sc = exact_score(W1, in1, cb + (size_t)c * DS);
                        if (sc > vb1 || (sc == vb1 && c < vi1)) { vb1 = sc; vi1 = c; }
                    }
                }
            }
        }
        // reduce (max score, min index) across the 4 lanes of each row
        #pragma unroll
        for (int off = 1; off < 4; off <<= 1) {
            float os = __shfl_xor_sync(~0u, vb0, off);
            int   oi = __shfl_xor_sync(~0u, vi0, off);
            if (os > vb0 || (os == vb0 && oi < vi0)) { vb0 = os; vi0 = oi; }
            os = __shfl_xor_sync(~0u, vb1, off);
            oi = __shfl_xor_sync(~0u, vi1, off);
            if (os > vb1 || (os == vb1 && oi < vi1)) { vb1 = os; vi1 = oi; }
        }
        if (lr == 0) {
            stage_row(s0, vi0, rs0, cb);
            stage_row(s1, vi1, rs1, cb);
        }
    }
}

// ---------------------------------------------------------------------------
// GEMM (round-7 config: 256 thr, warp tile 64x32, 113.4 us measured)
// ---------------------------------------------------------------------------
#define P_BY 400
#define A_SM_BYTES (128 * P_BY)
#define GEMM_SMEM  (2 * A_SM_BYTES)

__global__ __launch_bounds__(256) void gemm_mma_kernel(float* __restrict__ out)
{
    extern __shared__ __align__(16) unsigned char smem[];
    const int tid = threadIdx.x, wid = tid >> 5, lane = tid & 31;
    const int nb = blockIdx.x, mb = blockIdx.y;
    {
        const uint4* gA = (const uint4*)(g_Aext + (size_t)mb * 128 * KE);
        const uint4* gB = (const uint4*)(g_Bext + (size_t)nb * 128 * KE);
        #pragma unroll
        for (int it = 0; it < 12; ++it) {
            const int idx = tid + it * 256;
            const int r = idx / 24, j = idx % 24;
            *(uint4*)(smem + r * P_BY + j * 16)              = gA[idx];
            *(uint4*)(smem + A_SM_BYTES + r * P_BY + j * 16) = gB[idx];
        }
    }
    __syncthreads();
    const uint32_t sbase = smem_u32(smem);
    const int wm = wid >> 2, wn = wid & 3;
    const int aRow = lane & 15, aKof = (lane >> 4) * 16;
    const int g8 = lane >> 3;
    const int bRow = ((g8 & 2) ? 8 : 0) + (lane & 7), bKof = (g8 & 1) * 16;
    const uint32_t aAddr = sbase + (uint32_t)((wm * 64 + aRow) * P_BY + aKof);
    const uint32_t bAddr = sbase + A_SM_BYTES
                         + (uint32_t)((wn * 32 + bRow) * P_BY + bKof);
    float acc[4][4][4];
    #pragma unroll
    for (int i = 0; i < 4; ++i)
        #pragma unroll
        for (int j = 0; j < 4; ++j)
            #pragma unroll
            for (int e = 0; e < 4; ++e) acc[i][j][e] = 0.0f;
    #pragma unroll
    for (int ks = 0; ks < 12; ++ks) {
        const uint32_t kb = ks * 32;
        uint32_t a[4][4], b[2][4];
        #pragma unroll
        for (int mt = 0; mt < 4; ++mt)
            ldsm4(a[mt][0], a[mt][1], a[mt][2], a[mt][3], aAddr + mt * 16 * P_BY + kb);
        #pragma unroll
        for (int bt = 0; bt < 2; ++bt)
            ldsm4(b[bt][0], b[bt][1], b[bt][2], b[bt][3], bAddr + bt * 16 * P_BY + kb);
        #pragma unroll
        for (int mt = 0; mt < 4; ++mt)
            #pragma unroll
            for (int nt = 0; nt < 4; ++nt)
                mma16816(acc[mt][nt], a[mt],
                         b[nt >> 1][(nt & 1) * 2], b[nt >> 1][(nt & 1) * 2 + 1]);
    }
    const int r = lane >> 2, cp = (lane & 3) * 2;
    float* obase = out + (size_t)(mb * 128 + wm * 64) * N_COLS_B + nb * 128 + wn * 32;
    #pragma unroll
    for (int mt = 0; mt < 4; ++mt)
        #pragma unroll
        for (int nt = 0; nt < 4; ++nt) {
            float* o0 = obase + (size_t)(mt * 16 + r) * N_COLS_B + nt * 8 + cp;
            *(float2*)o0                  = make_float2(acc[mt][nt][0], acc[mt][nt][1]);
            *(float2*)(o0 + 8 * N_COLS_B) = make_float2(acc[mt][nt][2], acc[mt][nt][3]);
        }
}

extern "C" void kernel_launch(void* const* d_in, const int* in_sizes, int n_in,
                              void* d_out, int out_size)
{
    const float *U = nullptr, *B = nullptr, *rsU = nullptr, *rsB = nullptr, *cb = nullptr;
    for (int i = 0; i < n_in; ++i) {
        switch (in_sizes[i]) {
            case N_ROWS_U * RANK:  U   = (const float*)d_in[i]; break;
            case RANK * N_COLS_B:  B   = (const float*)d_in[i]; break;
            case N_ROWS_U:         rsU = (const float*)d_in[i]; break;
            case RANK:             rsB = (const float*)d_in[i]; break;
            case KCB * DS:         cb  = (const float*)d_in[i]; break;
            default: break;
        }
    }
    if (!U || !B || !rsU || !rsB || !cb) {
        U = (const float*)d_in[0]; B = (const float*)d_in[1];
        rsU = (const float*)d_in[2]; rsB = (const float*)d_in[3];
        cb = (const float*)d_in[4];
    }

    cudaFuncSetAttribute(score_kernel,
                         cudaFuncAttributeMaxDynamicSharedMemorySize, Q_SMEM);
    cudaFuncSetAttribute(gemm_mma_kernel,
                         cudaFuncAttributeMaxDynamicSharedMemorySize, GEMM_SMEM);

    prep_cb<<<KCB / 128, 128>>>(cb);
    prep_g<<<TOTAL_SUBS / 128, 128>>>(U, B, rsU, rsB);
    score_kernel<<<148, 384, Q_SMEM>>>(U, B, rsU, rsB, cb);
    gemm_mma_kernel<<<dim3(N_COLS_B / 128, N_ROWS_U / 128), 256, GEMM_SMEM>>>((float*)d_out);
}